// round 15
// baseline (speedup 1.0000x reference)
#include <cuda_runtime.h>
#include <cuda_fp16.h>

#define N_NODES 50000
#define N_TILES 3125         // 16 nodes per mma tile (50000 = 16*3125 exactly)
#define E_EDGES 800000
#define IN_C    16
#define HDIM    64
#define HH      32
#define NLAYERS 3
#define FULL    0xffffffffu

// Scratch (device globals)
__device__ float4 g_hf[N_TILES * 512];   // h in mma-fragment layout: [tile][lane][8 float4]
__device__ uint4  g_ph4[N_NODES * 4];    // p fp16 row-major [n][32] (64B/node)
__device__ uint4  g_qh4[N_NODES * 4];    // q fp16 row-major [n][32] (64B/node)
__device__ float  g_cnt[N_NODES];
__device__ uint4  g_epack[E_EDGES];      // {src|dst<<16, e0, e1, e2} per edge

// fp16 B-operand fragments, packed once per run
__device__ uint2 g_w2f[NLAYERS * 16 * 32];  // stage-2: [l][(j*2+s)][lane]
__device__ uint2 g_w1f[NLAYERS * 16 * 32];  // p-next:  [l][(jn*4+s)][lane]
__device__ uint2 g_dw1f[16 * 32];
__device__ uint2 g_vw1f[16 * 32];

__device__ __forceinline__ unsigned pack_half2(float lo, float hi) {
    __half2 h = __floats2half2_rn(lo, hi);
    return *reinterpret_cast<unsigned*>(&h);
}
__device__ __forceinline__ float2 unpack_half2(unsigned u) {
    return __half22float2(*reinterpret_cast<__half2*>(&u));
}
__device__ __forceinline__ void red_add_v4_f16x2(__half* ptr, unsigned a, unsigned b,
                                                 unsigned c, unsigned d) {
    asm volatile("red.global.add.noftz.v4.f16x2 [%0], {%1,%2,%3,%4};"
                 :: "l"(ptr), "r"(a), "r"(b), "r"(c), "r"(d) : "memory");
}
__device__ __forceinline__ void hmma(float* c, const unsigned* a, unsigned b0, unsigned b1) {
    asm volatile("mma.sync.aligned.m16n8k16.row.col.f32.f16.f16.f32 "
                 "{%0,%1,%2,%3}, {%4,%5,%6,%7}, {%8,%9}, {%0,%1,%2,%3};"
                 : "+f"(c[0]), "+f"(c[1]), "+f"(c[2]), "+f"(c[3])
                 : "r"(a[0]), "r"(a[1]), "r"(a[2]), "r"(a[3]), "r"(b0), "r"(b1));
}
__device__ __forceinline__ void ldmx4(unsigned* r, unsigned addr) {
    asm volatile("ldmatrix.sync.aligned.m8n8.x4.shared.b16 {%0,%1,%2,%3}, [%4];"
                 : "=r"(r[0]), "=r"(r[1]), "=r"(r[2]), "=r"(r[3]) : "r"(addr));
}

// ---------------- edge record pack (once per run) ----------------
__global__ void pack_edges_kernel(const int* __restrict__ ei, const float* __restrict__ ea) {
    int e = blockIdx.x * blockDim.x + threadIdx.x;
    if (e >= E_EDGES) return;
    unsigned src = (unsigned)__ldg(&ei[e]);
    unsigned dst = (unsigned)__ldg(&ei[E_EDGES + e]);
    g_epack[e] = make_uint4(src | (dst << 16),
                            __float_as_uint(__ldg(&ea[e * 3 + 0])),
                            __float_as_uint(__ldg(&ea[e * 3 + 1])),
                            __float_as_uint(__ldg(&ea[e * 3 + 2])));
}

// ---------------- weight fragment pack (once per run) ----------------
__global__ void pack_kernel(const float* __restrict__ mlp_w1,
                            const float* __restrict__ mlp_w2,
                            const float* __restrict__ dw1,
                            const float* __restrict__ vw1)
{
    int idx = blockIdx.x * blockDim.x + threadIdx.x;
    if (idx >= 128 * 32) return;
    int lane = idx & 31, frag = idx >> 5;
    int g = lane >> 2, t = lane & 3;

    if (frag < 48) {               // w2f
        int s = frag & 1, rest = frag >> 1, j = rest & 7, l = rest >> 3;
        const float* W = mlp_w2 + (size_t)l * 32 * 64;
        int n = 8 * j + g, k0 = 16 * s;
        g_w2f[idx] = make_uint2(
            pack_half2(W[(k0 + 2 * t) * 64 + n],     W[(k0 + 2 * t + 1) * 64 + n]),
            pack_half2(W[(k0 + 8 + 2 * t) * 64 + n], W[(k0 + 9 + 2 * t) * 64 + n]));
    } else if (frag < 96) {        // w1f
        int f = frag - 48;
        int s = f & 3, rest = f >> 2, jn = rest & 3, l = rest >> 2;
        const float* W = mlp_w1 + (size_t)l * 67 * 32;
        int n = 8 * jn + g, k0 = 16 * s;
        g_w1f[f * 32 + lane] = make_uint2(
            pack_half2(W[(k0 + 2 * t) * 32 + n],     W[(k0 + 2 * t + 1) * 32 + n]),
            pack_half2(W[(k0 + 8 + 2 * t) * 32 + n], W[(k0 + 9 + 2 * t) * 32 + n]));
    } else if (frag < 112) {       // dw1f
        int f = frag - 96;
        int s = f & 3, jn = f >> 2;
        int n = 8 * jn + g, k0 = 16 * s;
        g_dw1f[f * 32 + lane] = make_uint2(
            pack_half2(dw1[(k0 + 2 * t) * 32 + n],     dw1[(k0 + 2 * t + 1) * 32 + n]),
            pack_half2(dw1[(k0 + 8 + 2 * t) * 32 + n], dw1[(k0 + 9 + 2 * t) * 32 + n]));
    } else {                       // vw1f
        int f = frag - 112;
        int s = f & 3, jn = f >> 2;
        int n = 8 * jn + g, k0 = 16 * s;
        g_vw1f[f * 32 + lane] = make_uint2(
            pack_half2(vw1[(k0 + 2 * t) * 32 + n],     vw1[(k0 + 2 * t + 1) * 32 + n]),
            pack_half2(vw1[(k0 + 8 + 2 * t) * 32 + n], vw1[(k0 + 9 + 2 * t) * 32 + n]));
    }
}

// ---------------- encoder: h (fragment layout) + p0(fp16) + zero q/cnt ----------------
__global__ __launch_bounds__(256) void encoder_kernel(
    const float* __restrict__ x,  const float* __restrict__ w,
    const float* __restrict__ b,  const float* __restrict__ g,
    const float* __restrict__ beta,
    const float* __restrict__ w1, const float* __restrict__ b1)
{
    __shared__ float hstage[32][68];
    int wl   = threadIdx.x >> 5;
    int lane = threadIdx.x & 31;
    int n0   = blockIdx.x * 32 + wl * 4;
    bool act = (n0 < N_NODES);

    float h0[4], h1[4];
    if (act) {
        float xv[4], a0[4], a1[4];
#pragma unroll
        for (int i = 0; i < 4; i++) {
            xv[i] = (lane < IN_C) ? x[(n0 + i) * IN_C + lane] : 0.0f;
            a0[i] = __ldg(&b[lane]);
            a1[i] = __ldg(&b[lane + 32]);
        }
#pragma unroll
        for (int k = 0; k < IN_C; k++) {
            float w0 = __ldg(&w[k * HDIM + lane]);
            float w1v = __ldg(&w[k * HDIM + 32 + lane]);
#pragma unroll
            for (int i = 0; i < 4; i++) {
                float xk = __shfl_sync(FULL, xv[i], k);
                a0[i] = fmaf(xk, w0, a0[i]);
                a1[i] = fmaf(xk, w1v, a1[i]);
            }
        }
        float gl = __ldg(&g[lane]), gh = __ldg(&g[lane + 32]);
        float bl = __ldg(&beta[lane]), bh = __ldg(&beta[lane + 32]);
#pragma unroll
        for (int i = 0; i < 4; i++) {
            float s1 = a0[i] + a1[i], s2 = a0[i] * a0[i] + a1[i] * a1[i];
#pragma unroll
            for (int o = 16; o; o >>= 1) {
                s1 += __shfl_xor_sync(FULL, s1, o);
                s2 += __shfl_xor_sync(FULL, s2, o);
            }
            float mu  = s1 * (1.0f / 64.0f);
            float var = s2 * (1.0f / 64.0f) - mu * mu;
            float rs  = rsqrtf(var + 1e-5f);
            h0[i] = fmaxf(fmaf((a0[i] - mu) * rs, gl, bl), 0.0f);
            h1[i] = fmaxf(fmaf((a1[i] - mu) * rs, gh, bh), 0.0f);
            hstage[wl * 4 + i][lane]      = h0[i];
            hstage[wl * 4 + i][lane + 32] = h1[i];
        }
        float acc[4];
#pragma unroll
        for (int i = 0; i < 4; i++) acc[i] = __ldg(&b1[lane]);
#pragma unroll
        for (int k = 0; k < 32; k++) {
            float wk = __ldg(&w1[k * HH + lane]);
#pragma unroll
            for (int i = 0; i < 4; i++)
                acc[i] = fmaf(__shfl_sync(FULL, h0[i], k), wk, acc[i]);
        }
#pragma unroll
        for (int k = 0; k < 32; k++) {
            float wk = __ldg(&w1[(32 + k) * HH + lane]);
#pragma unroll
            for (int i = 0; i < 4; i++)
                acc[i] = fmaf(__shfl_sync(FULL, h1[i], k), wk, acc[i]);
        }
        unsigned* ph = (unsigned*)g_ph4;
#pragma unroll
        for (int i = 0; i < 4; i++) {
            float pr = __shfl_xor_sync(FULL, acc[i], 1);
            if ((lane & 1) == 0)
                ph[(size_t)(n0 + i) * 16 + (lane >> 1)] = pack_half2(acc[i], pr);
        }
        if (lane < 16) g_qh4[n0 * 4 + lane] = make_uint4(0, 0, 0, 0);
        if (lane < 4)  g_cnt[n0 + lane] = 0.0f;
    }
    __syncthreads();

    // warps 0,1 write the two 16-node tiles in fragment layout
    if (wl < 2) {
        int tile = blockIdx.x * 2 + wl;
        if (tile < N_TILES) {
            int gq = lane >> 2, tq = lane & 3;
            int r0 = wl * 16 + gq, r1 = r0 + 8;
            float4* hfo = g_hf + (size_t)tile * 512 + lane * 8;
#pragma unroll
            for (int j = 0; j < 8; j++) {
                float2 lo = *(float2*)&hstage[r0][2 * tq + 8 * j];
                float2 hi = *(float2*)&hstage[r1][2 * tq + 8 * j];
                hfo[j] = make_float4(lo.x, lo.y, hi.x, hi.y);
            }
        }
    }
}

// ------- edge kernel: 4 threads/edge; one 16B broadcast record; fp16 RED -------
template<bool COUNT>
__global__ __launch_bounds__(256) void edge_kernel(const float* __restrict__ w1)
{
    int idx = blockIdx.x * blockDim.x + threadIdx.x;
    int e = idx >> 2, q0 = idx & 3;
    if (e >= E_EDGES) return;

    uint4 rec = __ldg(&g_epack[e]);
    int src = rec.x & 0xFFFF;
    int dst = rec.x >> 16;
    float e0 = __uint_as_float(rec.y);
    float e1 = __uint_as_float(rec.z);
    float e2 = __uint_as_float(rec.w);

    uint4 praw = __ldg(&g_ph4[src * 4 + q0]);
    float2 p01 = unpack_half2(praw.x);
    float2 p23 = unpack_half2(praw.y);
    float2 p45 = unpack_half2(praw.z);
    float2 p67 = unpack_half2(praw.w);
    float p[8] = { p01.x, p01.y, p23.x, p23.y, p45.x, p45.y, p67.x, p67.y };

    const float4* W = (const float4*)(w1 + 64 * HH);
    float v[8];
#pragma unroll
    for (int s = 0; s < 2; s++) {
        int quad = 2 * q0 + s;
        float4 wa = __ldg(&W[quad]);
        float4 wb = __ldg(&W[8 + quad]);
        float4 wc = __ldg(&W[16 + quad]);
        v[4 * s + 0] = fmaxf(fmaf(e2, wc.x, fmaf(e1, wb.x, fmaf(e0, wa.x, p[4 * s + 0]))), 0.0f);
        v[4 * s + 1] = fmaxf(fmaf(e2, wc.y, fmaf(e1, wb.y, fmaf(e0, wa.y, p[4 * s + 1]))), 0.0f);
        v[4 * s + 2] = fmaxf(fmaf(e2, wc.z, fmaf(e1, wb.z, fmaf(e0, wa.z, p[4 * s + 2]))), 0.0f);
        v[4 * s + 3] = fmaxf(fmaf(e2, wc.w, fmaf(e1, wb.w, fmaf(e0, wa.w, p[4 * s + 3]))), 0.0f);
    }
    unsigned u0 = pack_half2(v[0], v[1]);
    unsigned u1 = pack_half2(v[2], v[3]);
    unsigned u2 = pack_half2(v[4], v[5]);
    unsigned u3 = pack_half2(v[6], v[7]);
    __half* qp = (__half*)g_qh4 + (size_t)dst * 32 + 8 * q0;
    red_add_v4_f16x2(qp, u0, u1, u2, u3);

    if (COUNT && q0 == 0) atomicAdd(&g_cnt[dst], 1.0f);
}

// ---- node_agg via HMMA: warp = 16-node tile ----
template<bool LAST>
__global__ __launch_bounds__(256) void node_agg_kernel(
    int layer,
    const float* __restrict__ b2,  const float* __restrict__ lng,
    const float* __restrict__ lnb, const float* __restrict__ b1n,
    const float* __restrict__ db1, const float* __restrict__ dw2,
    const float* __restrict__ db2, const float* __restrict__ vb1,
    const float* __restrict__ vw2, const float* __restrict__ vb2,
    float* __restrict__ out)
{
    __shared__ __align__(16) char qs[8][1280];
    int tid = threadIdx.x, w = tid >> 5, lane = tid & 31;
    int tile = blockIdx.x * 8 + w;
    if (tile >= N_TILES) return;
    int n0 = tile * 16;
    int g = lane >> 2, tq = lane & 3;

    // stage q fp16 into smem; zero q behind us
    {
        int nl = lane >> 1, half = lane & 1;
        uint4* src = (uint4*)g_qh4 + (size_t)(n0 + nl) * 4 + half * 2;
        uint4 v0 = src[0], v1 = src[1];
        src[0] = make_uint4(0, 0, 0, 0);
        src[1] = make_uint4(0, 0, 0, 0);
        *(uint4*)(qs[w] + nl * 80 + half * 32)      = v0;
        *(uint4*)(qs[w] + nl * 80 + half * 32 + 16) = v1;
    }
    __syncwarp();

    unsigned A0[4], A1[4];
    {
        unsigned base = (unsigned)__cvta_generic_to_shared(qs[w]);
        unsigned addr = base + (lane & 15) * 80 + ((lane >> 4) & 1) * 16;
        ldmx4(A0, addr);
        ldmx4(A1, addr + 32);
    }

    float acc[8][4];
#pragma unroll
    for (int j = 0; j < 8; j++) { acc[j][0] = acc[j][1] = acc[j][2] = acc[j][3] = 0.f; }
    const uint2* w2f = g_w2f + (size_t)layer * 16 * 32;
#pragma unroll
    for (int j = 0; j < 8; j++) {
        uint2 B0 = __ldg(&w2f[(j * 2 + 0) * 32 + lane]);
        uint2 B1 = __ldg(&w2f[(j * 2 + 1) * 32 + lane]);
        hmma(acc[j], A0, B0.x, B0.y);
        hmma(acc[j], A1, B1.x, B1.y);
    }

    float c0 = __ldg(&g_cnt[n0 + g]),     c1 = __ldg(&g_cnt[n0 + 8 + g]);
    float inv0 = (c0 > 0.f) ? (1.f / c0) : 0.f, has0 = (c0 > 0.f) ? 1.f : 0.f;
    float inv1 = (c1 > 0.f) ? (1.f / c1) : 0.f, has1 = (c1 > 0.f) ? 1.f : 0.f;

    const float2* b22 = (const float2*)b2;
    const float4* hf  = g_hf + (size_t)tile * 512 + lane * 8;
    float s10 = 0.f, s20 = 0.f, s11 = 0.f, s21 = 0.f;
#pragma unroll
    for (int j = 0; j < 8; j++) {
        float4 hp = __ldg(&hf[j]);
        float2 bb = __ldg(&b22[tq + 4 * j]);
        acc[j][0] = hp.x + acc[j][0] * inv0 + has0 * bb.x;
        acc[j][1] = hp.y + acc[j][1] * inv0 + has0 * bb.y;
        acc[j][2] = hp.z + acc[j][2] * inv1 + has1 * bb.x;
        acc[j][3] = hp.w + acc[j][3] * inv1 + has1 * bb.y;
        s10 += acc[j][0] + acc[j][1];
        s20 = fmaf(acc[j][0], acc[j][0], fmaf(acc[j][1], acc[j][1], s20));
        s11 += acc[j][2] + acc[j][3];
        s21 = fmaf(acc[j][2], acc[j][2], fmaf(acc[j][3], acc[j][3], s21));
    }
    s10 += __shfl_xor_sync(FULL, s10, 1); s10 += __shfl_xor_sync(FULL, s10, 2);
    s20 += __shfl_xor_sync(FULL, s20, 1); s20 += __shfl_xor_sync(FULL, s20, 2);
    s11 += __shfl_xor_sync(FULL, s11, 1); s11 += __shfl_xor_sync(FULL, s11, 2);
    s21 += __shfl_xor_sync(FULL, s21, 1); s21 += __shfl_xor_sync(FULL, s21, 2);
    float mu0 = s10 * (1.f / 64.f), var0 = s20 * (1.f / 64.f) - mu0 * mu0;
    float mu1 = s11 * (1.f / 64.f), var1 = s21 * (1.f / 64.f) - mu1 * mu1;
    float rs0 = rsqrtf(var0 + 1e-5f), rs1 = rsqrtf(var1 + 1e-5f);

    const float2* lg2 = (const float2*)lng;
    const float2* lb2 = (const float2*)lnb;
    float4* hfo = g_hf + (size_t)tile * 512 + lane * 8;
    unsigned Ah[4][4];
#pragma unroll
    for (int j = 0; j < 8; j++) {
        float2 gg = __ldg(&lg2[tq + 4 * j]);
        float2 bb = __ldg(&lb2[tq + 4 * j]);
        float v0 = fmaf((acc[j][0] - mu0) * rs0, gg.x, bb.x);
        float v1 = fmaf((acc[j][1] - mu0) * rs0, gg.y, bb.y);
        float v2 = fmaf((acc[j][2] - mu1) * rs1, gg.x, bb.x);
        float v3 = fmaf((acc[j][3] - mu1) * rs1, gg.y, bb.y);
        if (!LAST) hfo[j] = make_float4(v0, v1, v2, v3);
        if ((j & 1) == 0) {
            Ah[j >> 1][0] = pack_half2(v0, v1);
            Ah[j >> 1][1] = pack_half2(v2, v3);
        } else {
            Ah[j >> 1][2] = pack_half2(v0, v1);
            Ah[j >> 1][3] = pack_half2(v2, v3);
        }
    }

    if (!LAST) {
        const uint2* w1f = g_w1f + (size_t)(layer + 1) * 16 * 32;
        const float2* b1n2 = (const float2*)b1n;
        unsigned* ph = (unsigned*)g_ph4;
#pragma unroll
        for (int jn = 0; jn < 4; jn++) {
            float p[4] = {0.f, 0.f, 0.f, 0.f};
#pragma unroll
            for (int s = 0; s < 4; s++) {
                uint2 B = __ldg(&w1f[(jn * 4 + s) * 32 + lane]);
                hmma(p, Ah[s], B.x, B.y);
            }
            float2 bb = __ldg(&b1n2[tq + 4 * jn]);
            ph[(size_t)(n0 + g) * 16 + tq + 4 * jn]     = pack_half2(p[0] + bb.x, p[1] + bb.y);
            ph[(size_t)(n0 + 8 + g) * 16 + tq + 4 * jn] = pack_half2(p[2] + bb.x, p[3] + bb.y);
        }
    } else {
        const float2* db12 = (const float2*)db1;
        const float2* vb12 = (const float2*)vb1;
        const float2* dw22 = (const float2*)dw2;
        const float4* vw24 = (const float4*)vw2;
        float ds0 = 0.f, ds1 = 0.f, v00 = 0.f, v01 = 0.f, v10 = 0.f, v11 = 0.f;
#pragma unroll
        for (int jn = 0; jn < 4; jn++) {
            float dh[4] = {0.f, 0.f, 0.f, 0.f}, vh[4] = {0.f, 0.f, 0.f, 0.f};
#pragma unroll
            for (int s = 0; s < 4; s++) {
                uint2 Bd = __ldg(&g_dw1f[(jn * 4 + s) * 32 + lane]);
                uint2 Bv = __ldg(&g_vw1f[(jn * 4 + s) * 32 + lane]);
                hmma(dh, Ah[s], Bd.x, Bd.y);
                hmma(vh, Ah[s], Bv.x, Bv.y);
            }
            float2 dbb = __ldg(&db12[tq + 4 * jn]);
            float2 vbb = __ldg(&vb12[tq + 4 * jn]);
            float r0 = fmaxf(dh[0] + dbb.x, 0.f), r1 = fmaxf(dh[1] + dbb.y, 0.f);
            float r2 = fmaxf(dh[2] + dbb.x, 0.f), r3 = fmaxf(dh[3] + dbb.y, 0.f);
            float2 ww = __ldg(&dw22[tq + 4 * jn]);
            ds0 = fmaf(r0, ww.x, fmaf(r1, ww.y, ds0));
            ds1 = fmaf(r2, ww.x, fmaf(r3, ww.y, ds1));
            float q0v = fmaxf(vh[0] + vbb.x, 0.f), q1v = fmaxf(vh[1] + vbb.y, 0.f);
            float q2v = fmaxf(vh[2] + vbb.x, 0.f), q3v = fmaxf(vh[3] + vbb.y, 0.f);
            float4 vv = __ldg(&vw24[tq + 4 * jn]);
            v00 = fmaf(q0v, vv.x, fmaf(q1v, vv.z, v00));
            v01 = fmaf(q0v, vv.y, fmaf(q1v, vv.w, v01));
            v10 = fmaf(q2v, vv.x, fmaf(q3v, vv.z, v10));
            v11 = fmaf(q2v, vv.y, fmaf(q3v, vv.w, v11));
        }
        ds0 += __shfl_xor_sync(FULL, ds0, 1); ds0 += __shfl_xor_sync(FULL, ds0, 2);
        ds1 += __shfl_xor_sync(FULL, ds1, 1); ds1 += __shfl_xor_sync(FULL, ds1, 2);
        v00 += __shfl_xor_sync(FULL, v00, 1); v00 += __shfl_xor_sync(FULL, v00, 2);
        v01 += __shfl_xor_sync(FULL, v01, 1); v01 += __shfl_xor_sync(FULL, v01, 2);
        v10 += __shfl_xor_sync(FULL, v10, 1); v10 += __shfl_xor_sync(FULL, v10, 2);
        v11 += __shfl_xor_sync(FULL, v11, 1); v11 += __shfl_xor_sync(FULL, v11, 2);
        if (tq == 0) {
            float d2 = __ldg(&db2[0]);
            float vb0 = __ldg(&vb2[0]), vb1v = __ldg(&vb2[1]);
            out[n0 + g]     = ds0 + d2;
            out[n0 + 8 + g] = ds1 + d2;
            float2* vout = (float2*)(out + N_NODES);
            vout[n0 + g]     = make_float2(v00 + vb0, v01 + vb1v);
            vout[n0 + 8 + g] = make_float2(v10 + vb0, v11 + vb1v);
        }
    }
}

// ---------------- launch ----------------
extern "C" void kernel_launch(void* const* d_in, const int* in_sizes, int n_in,
                              void* d_out, int out_size)
{
    const float* x       = (const float*)d_in[0];
    const int*   ei      = (const int*)  d_in[1];
    const float* ea      = (const float*)d_in[2];
    const float* enc_w   = (const float*)d_in[3];
    const float* enc_b   = (const float*)d_in[4];
    const float* enc_g   = (const float*)d_in[5];
    const float* enc_bt  = (const float*)d_in[6];
    const float* mlp_w1  = (const float*)d_in[7];   // [L, 67, 32]
    const float* mlp_b1  = (const float*)d_in[8];   // [L, 32]
    const float* mlp_w2  = (const float*)d_in[9];   // [L, 32, 64]
    const float* mlp_b2  = (const float*)d_in[10];  // [L, 64]
    const float* ln_g    = (const float*)d_in[11];  // [L, 64]
    const float* ln_b    = (const float*)d_in[12];  // [L, 64]
    const float* dw1     = (const float*)d_in[13];
    const float* db1     = (const float*)d_in[14];
    const float* dw2     = (const float*)d_in[15];
    const float* db2     = (const float*)d_in[16];
    const float* vw1     = (const float*)d_in[17];
    const float* vb1     = (const float*)d_in[18];
    const float* vw2     = (const float*)d_in[19];
    const float* vb2     = (const float*)d_in[20];
    float* out = (float*)d_out;

    const int TB = 256;
    const int enc_grid  = (N_NODES + 31) / 32;
    const int node_grid = (N_TILES + 7) / 8;
    const int edge_grid = (E_EDGES * 4 + TB - 1) / TB;
    const int epk_grid  = (E_EDGES + TB - 1) / TB;

    pack_kernel<<<16, TB>>>(mlp_w1, mlp_w2, dw1, vw1);
    pack_edges_kernel<<<epk_grid, TB>>>(ei, ea);
    encoder_kernel<<<enc_grid, TB>>>(x, enc_w, enc_b, enc_g, enc_bt,
                                     mlp_w1, mlp_b1);

    for (int i = 0; i < NLAYERS; i++) {
        const float* w1 = mlp_w1 + (size_t)i * (HDIM + 3) * HH;
        const float* b2 = mlp_b2 + (size_t)i * HDIM;
        const float* lg = ln_g   + (size_t)i * HDIM;
        const float* lb = ln_b   + (size_t)i * HDIM;
        const float* b1n = mlp_b1 + (size_t)(i + 1) * HH;

        if (i == 0) edge_kernel<true ><<<edge_grid, TB>>>(w1);
        else        edge_kernel<false><<<edge_grid, TB>>>(w1);

        if (i + 1 < NLAYERS)
            node_agg_kernel<false><<<node_grid, TB>>>(i, b2, lg, lb, b1n,
                db1, dw2, db2, vb1, vw2, vb2, out);
        else
            node_agg_kernel<true ><<<node_grid, TB>>>(i, b2, lg, lb, nullptr,
                db1, dw2, db2, vb1, vw2, vb2, out);
    }
}

// round 16
// speedup vs baseline: 1.0281x; 1.0281x over previous
#include <cuda_runtime.h>
#include <cuda_fp16.h>

#define N_NODES 50000
#define N_TILES 3125         // 16 nodes per mma tile (50000 = 16*3125 exactly)
#define E_EDGES 800000
#define IN_C    16
#define HDIM    64
#define HH      32
#define NLAYERS 3
#define FULL    0xffffffffu

// Scratch (device globals)
__device__ float4 g_hf[N_TILES * 256];   // h fragment layout: [tile][lane][8 float4]
__device__ uint4  g_ph4[N_NODES * 4];    // p fp16 row-major [n][32] (64B/node)
__device__ uint4  g_qh4[N_NODES * 4];    // q fp16 row-major [n][32] (64B/node)
__device__ float  g_cnt[N_NODES];

// fp16 B-operand fragments, packed once per run
__device__ uint2 g_w2f[NLAYERS * 16 * 32];  // stage-2: [l][(j*2+s)][lane]
__device__ uint2 g_w1f[NLAYERS * 16 * 32];  // p-next:  [l][(jn*4+s)][lane]
__device__ uint2 g_dw1f[16 * 32];
__device__ uint2 g_vw1f[16 * 32];

__device__ __forceinline__ unsigned pack_half2(float lo, float hi) {
    __half2 h = __floats2half2_rn(lo, hi);
    return *reinterpret_cast<unsigned*>(&h);
}
__device__ __forceinline__ float2 unpack_half2(unsigned u) {
    return __half22float2(*reinterpret_cast<__half2*>(&u));
}
__device__ __forceinline__ void red_add_v4_f16x2(__half* ptr, unsigned a, unsigned b,
                                                 unsigned c, unsigned d) {
    asm volatile("red.global.add.noftz.v4.f16x2 [%0], {%1,%2,%3,%4};"
                 :: "l"(ptr), "r"(a), "r"(b), "r"(c), "r"(d) : "memory");
}
__device__ __forceinline__ void hmma(float* c, const unsigned* a, unsigned b0, unsigned b1) {
    asm volatile("mma.sync.aligned.m16n8k16.row.col.f32.f16.f16.f32 "
                 "{%0,%1,%2,%3}, {%4,%5,%6,%7}, {%8,%9}, {%0,%1,%2,%3};"
                 : "+f"(c[0]), "+f"(c[1]), "+f"(c[2]), "+f"(c[3])
                 : "r"(a[0]), "r"(a[1]), "r"(a[2]), "r"(a[3]), "r"(b0), "r"(b1));
}
__device__ __forceinline__ void ldmx4(unsigned* r, unsigned addr) {
    asm volatile("ldmatrix.sync.aligned.m8n8.x4.shared.b16 {%0,%1,%2,%3}, [%4];"
                 : "=r"(r[0]), "=r"(r[1]), "=r"(r[2]), "=r"(r[3]) : "r"(addr));
}

// ---------------- weight fragment pack (once per run) ----------------
__global__ void pack_kernel(const float* __restrict__ mlp_w1,
                            const float* __restrict__ mlp_w2,
                            const float* __restrict__ dw1,
                            const float* __restrict__ vw1)
{
    int idx = blockIdx.x * blockDim.x + threadIdx.x;
    if (idx >= 128 * 32) return;
    int lane = idx & 31, frag = idx >> 5;
    int g = lane >> 2, t = lane & 3;

    if (frag < 48) {               // w2f
        int s = frag & 1, rest = frag >> 1, j = rest & 7, l = rest >> 3;
        const float* W = mlp_w2 + (size_t)l * 32 * 64;
        int n = 8 * j + g, k0 = 16 * s;
        g_w2f[idx] = make_uint2(
            pack_half2(W[(k0 + 2 * t) * 64 + n],     W[(k0 + 2 * t + 1) * 64 + n]),
            pack_half2(W[(k0 + 8 + 2 * t) * 64 + n], W[(k0 + 9 + 2 * t) * 64 + n]));
    } else if (frag < 96) {        // w1f
        int f = frag - 48;
        int s = f & 3, rest = f >> 2, jn = rest & 3, l = rest >> 2;
        const float* W = mlp_w1 + (size_t)l * 67 * 32;
        int n = 8 * jn + g, k0 = 16 * s;
        g_w1f[f * 32 + lane] = make_uint2(
            pack_half2(W[(k0 + 2 * t) * 32 + n],     W[(k0 + 2 * t + 1) * 32 + n]),
            pack_half2(W[(k0 + 8 + 2 * t) * 32 + n], W[(k0 + 9 + 2 * t) * 32 + n]));
    } else if (frag < 112) {       // dw1f
        int f = frag - 96;
        int s = f & 3, jn = f >> 2;
        int n = 8 * jn + g, k0 = 16 * s;
        g_dw1f[f * 32 + lane] = make_uint2(
            pack_half2(dw1[(k0 + 2 * t) * 32 + n],     dw1[(k0 + 2 * t + 1) * 32 + n]),
            pack_half2(dw1[(k0 + 8 + 2 * t) * 32 + n], dw1[(k0 + 9 + 2 * t) * 32 + n]));
    } else {                       // vw1f
        int f = frag - 112;
        int s = f & 3, jn = f >> 2;
        int n = 8 * jn + g, k0 = 16 * s;
        g_vw1f[f * 32 + lane] = make_uint2(
            pack_half2(vw1[(k0 + 2 * t) * 32 + n],     vw1[(k0 + 2 * t + 1) * 32 + n]),
            pack_half2(vw1[(k0 + 8 + 2 * t) * 32 + n], vw1[(k0 + 9 + 2 * t) * 32 + n]));
    }
}

// ---------------- encoder: h (fragment layout) + p0(fp16) + zero q/cnt ----------------
__global__ __launch_bounds__(256) void encoder_kernel(
    const float* __restrict__ x,  const float* __restrict__ w,
    const float* __restrict__ b,  const float* __restrict__ g,
    const float* __restrict__ beta,
    const float* __restrict__ w1, const float* __restrict__ b1)
{
    __shared__ float hstage[32][68];
    int wl   = threadIdx.x >> 5;
    int lane = threadIdx.x & 31;
    int n0   = blockIdx.x * 32 + wl * 4;
    bool act = (n0 < N_NODES);

    float h0[4], h1[4];
    if (act) {
        float xv[4], a0[4], a1[4];
#pragma unroll
        for (int i = 0; i < 4; i++) {
            xv[i] = (lane < IN_C) ? x[(n0 + i) * IN_C + lane] : 0.0f;
            a0[i] = __ldg(&b[lane]);
            a1[i] = __ldg(&b[lane + 32]);
        }
#pragma unroll
        for (int k = 0; k < IN_C; k++) {
            float w0 = __ldg(&w[k * HDIM + lane]);
            float w1v = __ldg(&w[k * HDIM + 32 + lane]);
#pragma unroll
            for (int i = 0; i < 4; i++) {
                float xk = __shfl_sync(FULL, xv[i], k);
                a0[i] = fmaf(xk, w0, a0[i]);
                a1[i] = fmaf(xk, w1v, a1[i]);
            }
        }
        float gl = __ldg(&g[lane]), gh = __ldg(&g[lane + 32]);
        float bl = __ldg(&beta[lane]), bh = __ldg(&beta[lane + 32]);
#pragma unroll
        for (int i = 0; i < 4; i++) {
            float s1 = a0[i] + a1[i], s2 = a0[i] * a0[i] + a1[i] * a1[i];
#pragma unroll
            for (int o = 16; o; o >>= 1) {
                s1 += __shfl_xor_sync(FULL, s1, o);
                s2 += __shfl_xor_sync(FULL, s2, o);
            }
            float mu  = s1 * (1.0f / 64.0f);
            float var = s2 * (1.0f / 64.0f) - mu * mu;
            float rs  = rsqrtf(var + 1e-5f);
            h0[i] = fmaxf(fmaf((a0[i] - mu) * rs, gl, bl), 0.0f);
            h1[i] = fmaxf(fmaf((a1[i] - mu) * rs, gh, bh), 0.0f);
            hstage[wl * 4 + i][lane]      = h0[i];
            hstage[wl * 4 + i][lane + 32] = h1[i];
        }
        float acc[4];
#pragma unroll
        for (int i = 0; i < 4; i++) acc[i] = __ldg(&b1[lane]);
#pragma unroll
        for (int k = 0; k < 32; k++) {
            float wk = __ldg(&w1[k * HH + lane]);
#pragma unroll
            for (int i = 0; i < 4; i++)
                acc[i] = fmaf(__shfl_sync(FULL, h0[i], k), wk, acc[i]);
        }
#pragma unroll
        for (int k = 0; k < 32; k++) {
            float wk = __ldg(&w1[(32 + k) * HH + lane]);
#pragma unroll
            for (int i = 0; i < 4; i++)
                acc[i] = fmaf(__shfl_sync(FULL, h1[i], k), wk, acc[i]);
        }
        unsigned* ph = (unsigned*)g_ph4;
#pragma unroll
        for (int i = 0; i < 4; i++) {
            float pr = __shfl_xor_sync(FULL, acc[i], 1);
            if ((lane & 1) == 0)
                ph[(size_t)(n0 + i) * 16 + (lane >> 1)] = pack_half2(acc[i], pr);
        }
        if (lane < 16) g_qh4[n0 * 4 + lane] = make_uint4(0, 0, 0, 0);
        if (lane < 4)  g_cnt[n0 + lane] = 0.0f;
    }
    __syncthreads();

    // warps 0,1 write the two 16-node tiles in fragment layout
    if (wl < 2) {
        int tile = blockIdx.x * 2 + wl;
        if (tile < N_TILES) {
            int gq = lane >> 2, tq = lane & 3;
            int r0 = wl * 16 + gq, r1 = r0 + 8;
            float4* hfo = g_hf + (size_t)tile * 256 + lane * 8;
#pragma unroll
            for (int j = 0; j < 8; j++) {
                float2 lo = *(float2*)&hstage[r0][2 * tq + 8 * j];
                float2 hi = *(float2*)&hstage[r1][2 * tq + 8 * j];
                hfo[j] = make_float4(lo.x, lo.y, hi.x, hi.y);
            }
        }
    }
}

// ------- edge kernel: 4 threads/edge; fp16 p gather; fp16 v4.f16x2 RED -------
template<bool COUNT>
__global__ __launch_bounds__(256) void edge_kernel(
    const int* __restrict__ ei, const float* __restrict__ ea,
    const float* __restrict__ w1)
{
    int idx = blockIdx.x * blockDim.x + threadIdx.x;
    int e = idx >> 2, q0 = idx & 3;
    if (e >= E_EDGES) return;

    int src = __ldg(&ei[e]);
    int dst = __ldg(&ei[E_EDGES + e]);
    float e0 = __ldg(&ea[e * 3 + 0]);
    float e1 = __ldg(&ea[e * 3 + 1]);
    float e2 = __ldg(&ea[e * 3 + 2]);

    uint4 praw = __ldg(&g_ph4[src * 4 + q0]);
    float2 p01 = unpack_half2(praw.x);
    float2 p23 = unpack_half2(praw.y);
    float2 p45 = unpack_half2(praw.z);
    float2 p67 = unpack_half2(praw.w);
    float p[8] = { p01.x, p01.y, p23.x, p23.y, p45.x, p45.y, p67.x, p67.y };

    const float4* W = (const float4*)(w1 + 64 * HH);
    float v[8];
#pragma unroll
    for (int s = 0; s < 2; s++) {
        int quad = 2 * q0 + s;
        float4 wa = __ldg(&W[quad]);
        float4 wb = __ldg(&W[8 + quad]);
        float4 wc = __ldg(&W[16 + quad]);
        v[4 * s + 0] = fmaxf(fmaf(e2, wc.x, fmaf(e1, wb.x, fmaf(e0, wa.x, p[4 * s + 0]))), 0.0f);
        v[4 * s + 1] = fmaxf(fmaf(e2, wc.y, fmaf(e1, wb.y, fmaf(e0, wa.y, p[4 * s + 1]))), 0.0f);
        v[4 * s + 2] = fmaxf(fmaf(e2, wc.z, fmaf(e1, wb.z, fmaf(e0, wa.z, p[4 * s + 2]))), 0.0f);
        v[4 * s + 3] = fmaxf(fmaf(e2, wc.w, fmaf(e1, wb.w, fmaf(e0, wa.w, p[4 * s + 3]))), 0.0f);
    }
    unsigned u0 = pack_half2(v[0], v[1]);
    unsigned u1 = pack_half2(v[2], v[3]);
    unsigned u2 = pack_half2(v[4], v[5]);
    unsigned u3 = pack_half2(v[6], v[7]);
    __half* qp = (__half*)g_qh4 + (size_t)dst * 32 + 8 * q0;
    red_add_v4_f16x2(qp, u0, u1, u2, u3);

    if (COUNT && q0 == 0) atomicAdd(&g_cnt[dst], 1.0f);
}

// ---- node_agg via HMMA: warp = 16-node tile; 4 warps/block; early loads ----
template<bool LAST>
__global__ __launch_bounds__(128) void node_agg_kernel(
    int layer,
    const float* __restrict__ b2,  const float* __restrict__ lng,
    const float* __restrict__ lnb, const float* __restrict__ b1n,
    const float* __restrict__ db1, const float* __restrict__ dw2,
    const float* __restrict__ db2, const float* __restrict__ vb1,
    const float* __restrict__ vw2, const float* __restrict__ vb2,
    float* __restrict__ out)
{
    __shared__ __align__(16) char qs[4][1280];
    int tid = threadIdx.x, w = tid >> 5, lane = tid & 31;
    int tile = blockIdx.x * 4 + w;
    if (tile >= N_TILES) return;
    int n0 = tile * 16;
    int g = lane >> 2, tq = lane & 3;

    // early: prefetch this lane's hf line (exactly 128B) and load cnt
    const float4* hf = g_hf + (size_t)tile * 256 + lane * 8;
    asm volatile("prefetch.global.L1 [%0];" :: "l"(hf));
    float c0 = __ldg(&g_cnt[n0 + g]);
    float c1 = __ldg(&g_cnt[n0 + 8 + g]);

    // stage q fp16 into smem; zero q behind us
    {
        int nl = lane >> 1, half = lane & 1;
        uint4* src = (uint4*)g_qh4 + (size_t)(n0 + nl) * 4 + half * 2;
        uint4 v0 = src[0], v1 = src[1];
        src[0] = make_uint4(0, 0, 0, 0);
        src[1] = make_uint4(0, 0, 0, 0);
        *(uint4*)(qs[w] + nl * 80 + half * 32)      = v0;
        *(uint4*)(qs[w] + nl * 80 + half * 32 + 16) = v1;
    }
    __syncwarp();

    unsigned A0[4], A1[4];
    {
        unsigned base = (unsigned)__cvta_generic_to_shared(qs[w]);
        unsigned addr = base + (lane & 15) * 80 + ((lane >> 4) & 1) * 16;
        ldmx4(A0, addr);
        ldmx4(A1, addr + 32);
    }

    float acc[8][4];
#pragma unroll
    for (int j = 0; j < 8; j++) { acc[j][0] = acc[j][1] = acc[j][2] = acc[j][3] = 0.f; }
    const uint2* w2f = g_w2f + (size_t)layer * 16 * 32;
#pragma unroll
    for (int j = 0; j < 8; j++) {
        uint2 B0 = __ldg(&w2f[(j * 2 + 0) * 32 + lane]);
        uint2 B1 = __ldg(&w2f[(j * 2 + 1) * 32 + lane]);
        hmma(acc[j], A0, B0.x, B0.y);
        hmma(acc[j], A1, B1.x, B1.y);
    }

    float inv0 = (c0 > 0.f) ? (1.f / c0) : 0.f, has0 = (c0 > 0.f) ? 1.f : 0.f;
    float inv1 = (c1 > 0.f) ? (1.f / c1) : 0.f, has1 = (c1 > 0.f) ? 1.f : 0.f;

    const float2* b22 = (const float2*)b2;
    float s10 = 0.f, s20 = 0.f, s11 = 0.f, s21 = 0.f;
#pragma unroll
    for (int j = 0; j < 8; j++) {
        float4 hp = __ldg(&hf[j]);
        float2 bb = __ldg(&b22[tq + 4 * j]);
        acc[j][0] = hp.x + acc[j][0] * inv0 + has0 * bb.x;
        acc[j][1] = hp.y + acc[j][1] * inv0 + has0 * bb.y;
        acc[j][2] = hp.z + acc[j][2] * inv1 + has1 * bb.x;
        acc[j][3] = hp.w + acc[j][3] * inv1 + has1 * bb.y;
        s10 += acc[j][0] + acc[j][1];
        s20 = fmaf(acc[j][0], acc[j][0], fmaf(acc[j][1], acc[j][1], s20));
        s11 += acc[j][2] + acc[j][3];
        s21 = fmaf(acc[j][2], acc[j][2], fmaf(acc[j][3], acc[j][3], s21));
    }
    s10 += __shfl_xor_sync(FULL, s10, 1); s10 += __shfl_xor_sync(FULL, s10, 2);
    s20 += __shfl_xor_sync(FULL, s20, 1); s20 += __shfl_xor_sync(FULL, s20, 2);
    s11 += __shfl_xor_sync(FULL, s11, 1); s11 += __shfl_xor_sync(FULL, s11, 2);
    s21 += __shfl_xor_sync(FULL, s21, 1); s21 += __shfl_xor_sync(FULL, s21, 2);
    float mu0 = s10 * (1.f / 64.f), var0 = s20 * (1.f / 64.f) - mu0 * mu0;
    float mu1 = s11 * (1.f / 64.f), var1 = s21 * (1.f / 64.f) - mu1 * mu1;
    float rs0 = rsqrtf(var0 + 1e-5f), rs1 = rsqrtf(var1 + 1e-5f);

    const float2* lg2 = (const float2*)lng;
    const float2* lb2 = (const float2*)lnb;
    float4* hfo = g_hf + (size_t)tile * 256 + lane * 8;
    unsigned Ah[4][4];
#pragma unroll
    for (int j = 0; j < 8; j++) {
        float2 gg = __ldg(&lg2[tq + 4 * j]);
        float2 bb = __ldg(&lb2[tq + 4 * j]);
        float v0 = fmaf((acc[j][0] - mu0) * rs0, gg.x, bb.x);
        float v1 = fmaf((acc[j][1] - mu0) * rs0, gg.y, bb.y);
        float v2 = fmaf((acc[j][2] - mu1) * rs1, gg.x, bb.x);
        float v3 = fmaf((acc[j][3] - mu1) * rs1, gg.y, bb.y);
        if (!LAST) hfo[j] = make_float4(v0, v1, v2, v3);
        if ((j & 1) == 0) {
            Ah[j >> 1][0] = pack_half2(v0, v1);
            Ah[j >> 1][1] = pack_half2(v2, v3);
        } else {
            Ah[j >> 1][2] = pack_half2(v0, v1);
            Ah[j >> 1][3] = pack_half2(v2, v3);
        }
    }

    if (!LAST) {
        const uint2* w1f = g_w1f + (size_t)(layer + 1) * 16 * 32;
        const float2* b1n2 = (const float2*)b1n;
        unsigned* ph = (unsigned*)g_ph4;
#pragma unroll
        for (int jn = 0; jn < 4; jn++) {
            float p[4] = {0.f, 0.f, 0.f, 0.f};
#pragma unroll
            for (int s = 0; s < 4; s++) {
                uint2 B = __ldg(&w1f[(jn * 4 + s) * 32 + lane]);
                hmma(p, Ah[s], B.x, B.y);
            }
            float2 bb = __ldg(&b1n2[tq + 4 * jn]);
            ph[(size_t)(n0 + g) * 16 + tq + 4 * jn]     = pack_half2(p[0] + bb.x, p[1] + bb.y);
            ph[(size_t)(n0 + 8 + g) * 16 + tq + 4 * jn] = pack_half2(p[2] + bb.x, p[3] + bb.y);
        }
    } else {
        const float2* db12 = (const float2*)db1;
        const float2* vb12 = (const float2*)vb1;
        const float2* dw22 = (const float2*)dw2;
        const float4* vw24 = (const float4*)vw2;
        float ds0 = 0.f, ds1 = 0.f, v00 = 0.f, v01 = 0.f, v10 = 0.f, v11 = 0.f;
#pragma unroll
        for (int jn = 0; jn < 4; jn++) {
            float dh[4] = {0.f, 0.f, 0.f, 0.f}, vh[4] = {0.f, 0.f, 0.f, 0.f};
#pragma unroll
            for (int s = 0; s < 4; s++) {
                uint2 Bd = __ldg(&g_dw1f[(jn * 4 + s) * 32 + lane]);
                uint2 Bv = __ldg(&g_vw1f[(jn * 4 + s) * 32 + lane]);
                hmma(dh, Ah[s], Bd.x, Bd.y);
                hmma(vh, Ah[s], Bv.x, Bv.y);
            }
            float2 dbb = __ldg(&db12[tq + 4 * jn]);
            float2 vbb = __ldg(&vb12[tq + 4 * jn]);
            float r0 = fmaxf(dh[0] + dbb.x, 0.f), r1 = fmaxf(dh[1] + dbb.y, 0.f);
            float r2 = fmaxf(dh[2] + dbb.x, 0.f), r3 = fmaxf(dh[3] + dbb.y, 0.f);
            float2 ww = __ldg(&dw22[tq + 4 * jn]);
            ds0 = fmaf(r0, ww.x, fmaf(r1, ww.y, ds0));
            ds1 = fmaf(r2, ww.x, fmaf(r3, ww.y, ds1));
            float q0v = fmaxf(vh[0] + vbb.x, 0.f), q1v = fmaxf(vh[1] + vbb.y, 0.f);
            float q2v = fmaxf(vh[2] + vbb.x, 0.f), q3v = fmaxf(vh[3] + vbb.y, 0.f);
            float4 vv = __ldg(&vw24[tq + 4 * jn]);
            v00 = fmaf(q0v, vv.x, fmaf(q1v, vv.z, v00));
            v01 = fmaf(q0v, vv.y, fmaf(q1v, vv.w, v01));
            v10 = fmaf(q2v, vv.x, fmaf(q3v, vv.z, v10));
            v11 = fmaf(q2v, vv.y, fmaf(q3v, vv.w, v11));
        }
        ds0 += __shfl_xor_sync(FULL, ds0, 1); ds0 += __shfl_xor_sync(FULL, ds0, 2);
        ds1 += __shfl_xor_sync(FULL, ds1, 1); ds1 += __shfl_xor_sync(FULL, ds1, 2);
        v00 += __shfl_xor_sync(FULL, v00, 1); v00 += __shfl_xor_sync(FULL, v00, 2);
        v01 += __shfl_xor_sync(FULL, v01, 1); v01 += __shfl_xor_sync(FULL, v01, 2);
        v10 += __shfl_xor_sync(FULL, v10, 1); v10 += __shfl_xor_sync(FULL, v10, 2);
        v11 += __shfl_xor_sync(FULL, v11, 1); v11 += __shfl_xor_sync(FULL, v11, 2);
        if (tq == 0) {
            float d2 = __ldg(&db2[0]);
            float vb0 = __ldg(&vb2[0]), vb1v = __ldg(&vb2[1]);
            out[n0 + g]     = ds0 + d2;
            out[n0 + 8 + g] = ds1 + d2;
            float2* vout = (float2*)(out + N_NODES);
            vout[n0 + g]     = make_float2(v00 + vb0, v01 + vb1v);
            vout[n0 + 8 + g] = make_float2(v10 + vb0, v11 + vb1v);
        }
    }
}

// ---------------- launch ----------------
extern "C" void kernel_launch(void* const* d_in, const int* in_sizes, int n_in,
                              void* d_out, int out_size)
{
    const float* x       = (const float*)d_in[0];
    const int*   ei      = (const int*)  d_in[1];
    const float* ea      = (const float*)d_in[2];
    const float* enc_w   = (const float*)d_in[3];
    const float* enc_b   = (const float*)d_in[4];
    const float* enc_g   = (const float*)d_in[5];
    const float* enc_bt  = (const float*)d_in[6];
    const float* mlp_w1  = (const float*)d_in[7];   // [L, 67, 32]
    const float* mlp_b1  = (const float*)d_in[8];   // [L, 32]
    const float* mlp_w2  = (const float*)d_in[9];   // [L, 32, 64]
    const float* mlp_b2  = (const float*)d_in[10];  // [L, 64]
    const float* ln_g    = (const float*)d_in[11];  // [L, 64]
    const float* ln_b    = (const float*)d_in[12];  // [L, 64]
    const float* dw1     = (const float*)d_in[13];
    const float* db1     = (const float*)d_in[14];
    const float* dw2     = (const float*)d_in[15];
    const float* db2     = (const float*)d_in[16];
    const float* vw1     = (const float*)d_in[17];
    const float* vb1     = (const float*)d_in[18];
    const float* vw2     = (const float*)d_in[19];
    const float* vb2     = (const float*)d_in[20];
    float* out = (float*)d_out;

    const int TB = 256;
    const int enc_grid  = (N_NODES + 31) / 32;
    const int node_grid = (N_TILES + 3) / 4;                  // 4 tiles/block, 128 thr
    const int edge_grid = (E_EDGES * 4 + TB - 1) / TB;

    pack_kernel<<<16, TB>>>(mlp_w1, mlp_w2, dw1, vw1);
    encoder_kernel<<<enc_grid, TB>>>(x, enc_w, enc_b, enc_g, enc_bt,
                                     mlp_w1, mlp_b1);

    for (int i = 0; i < NLAYERS; i++) {
        const float* w1 = mlp_w1 + (size_t)i * (HDIM + 3) * HH;
        const float* b2 = mlp_b2 + (size_t)i * HDIM;
        const float* lg = ln_g   + (size_t)i * HDIM;
        const float* lb = ln_b   + (size_t)i * HDIM;
        const float* b1n = mlp_b1 + (size_t)(i + 1) * HH;

        if (i == 0) edge_kernel<true ><<<edge_grid, TB>>>(ei, ea, w1);
        else        edge_kernel<false><<<edge_grid, TB>>>(ei, ea, w1);

        if (i + 1 < NLAYERS)
            node_agg_kernel<false><<<node_grid, 128>>>(i, b2, lg, lb, b1n,
                db1, dw2, db2, vb1, vw2, vb2, out);
        else
            node_agg_kernel<true ><<<node_grid, 128>>>(i, b2, lg, lb, nullptr,
                db1, dw2, db2, vb1, vw2, vb2, out);
    }
}

// round 17
// speedup vs baseline: 1.1398x; 1.1087x over previous
#include <cuda_runtime.h>
#include <cuda_fp16.h>

#define N_NODES 50000
#define N_TILES 3125         // 16 nodes per mma tile (50000 = 16*3125 exactly)
#define E_EDGES 800000
#define IN_C    16
#define HDIM    64
#define HH      32
#define NLAYERS 3
#define FULL    0xffffffffu

// Scratch (device globals)
__device__ float4 g_hf[N_TILES * 256];   // h fragment layout: [tile][lane][8 float4]
__device__ uint4  g_ph4[N_NODES * 4];    // p fp16 row-major [n][32] (64B/node)
__device__ uint4  g_qh4[N_NODES * 4];    // q fp16 row-major [n][32] (64B/node)
__device__ float  g_cnt[N_NODES];

// fp16 B-operand fragments, packed once per run
__device__ uint2 g_w2f[NLAYERS * 16 * 32];  // stage-2: [l][(j*2+s)][lane]
__device__ uint2 g_w1f[NLAYERS * 16 * 32];  // p-next:  [l][(jn*4+s)][lane]
__device__ uint2 g_dw1f[16 * 32];
__device__ uint2 g_vw1f[16 * 32];

__device__ __forceinline__ unsigned pack_half2(float lo, float hi) {
    __half2 h = __floats2half2_rn(lo, hi);
    return *reinterpret_cast<unsigned*>(&h);
}
__device__ __forceinline__ float2 unpack_half2(unsigned u) {
    return __half22float2(*reinterpret_cast<__half2*>(&u));
}
__device__ __forceinline__ void red_add_v4_f16x2(__half* ptr, unsigned a, unsigned b,
                                                 unsigned c, unsigned d) {
    asm volatile("red.global.add.noftz.v4.f16x2 [%0], {%1,%2,%3,%4};"
                 :: "l"(ptr), "r"(a), "r"(b), "r"(c), "r"(d) : "memory");
}
__device__ __forceinline__ void hmma(float* c, const unsigned* a, unsigned b0, unsigned b1) {
    asm volatile("mma.sync.aligned.m16n8k16.row.col.f32.f16.f16.f32 "
                 "{%0,%1,%2,%3}, {%4,%5,%6,%7}, {%8,%9}, {%0,%1,%2,%3};"
                 : "+f"(c[0]), "+f"(c[1]), "+f"(c[2]), "+f"(c[3])
                 : "r"(a[0]), "r"(a[1]), "r"(a[2]), "r"(a[3]), "r"(b0), "r"(b1));
}
__device__ __forceinline__ void ldmx4(unsigned* r, unsigned addr) {
    asm volatile("ldmatrix.sync.aligned.m8n8.x4.shared.b16 {%0,%1,%2,%3}, [%4];"
                 : "=r"(r[0]), "=r"(r[1]), "=r"(r[2]), "=r"(r[3]) : "r"(addr));
}

// ---------------- weight fragment pack (once per run) ----------------
__global__ void pack_kernel(const float* __restrict__ mlp_w1,
                            const float* __restrict__ mlp_w2,
                            const float* __restrict__ dw1,
                            const float* __restrict__ vw1)
{
    int idx = blockIdx.x * blockDim.x + threadIdx.x;
    if (idx >= 128 * 32) return;
    int lane = idx & 31, frag = idx >> 5;
    int g = lane >> 2, t = lane & 3;

    if (frag < 48) {               // w2f
        int s = frag & 1, rest = frag >> 1, j = rest & 7, l = rest >> 3;
        const float* W = mlp_w2 + (size_t)l * 32 * 64;
        int n = 8 * j + g, k0 = 16 * s;
        g_w2f[idx] = make_uint2(
            pack_half2(W[(k0 + 2 * t) * 64 + n],     W[(k0 + 2 * t + 1) * 64 + n]),
            pack_half2(W[(k0 + 8 + 2 * t) * 64 + n], W[(k0 + 9 + 2 * t) * 64 + n]));
    } else if (frag < 96) {        // w1f
        int f = frag - 48;
        int s = f & 3, rest = f >> 2, jn = rest & 3, l = rest >> 2;
        const float* W = mlp_w1 + (size_t)l * 67 * 32;
        int n = 8 * jn + g, k0 = 16 * s;
        g_w1f[f * 32 + lane] = make_uint2(
            pack_half2(W[(k0 + 2 * t) * 32 + n],     W[(k0 + 2 * t + 1) * 32 + n]),
            pack_half2(W[(k0 + 8 + 2 * t) * 32 + n], W[(k0 + 9 + 2 * t) * 32 + n]));
    } else if (frag < 112) {       // dw1f
        int f = frag - 96;
        int s = f & 3, jn = f >> 2;
        int n = 8 * jn + g, k0 = 16 * s;
        g_dw1f[f * 32 + lane] = make_uint2(
            pack_half2(dw1[(k0 + 2 * t) * 32 + n],     dw1[(k0 + 2 * t + 1) * 32 + n]),
            pack_half2(dw1[(k0 + 8 + 2 * t) * 32 + n], dw1[(k0 + 9 + 2 * t) * 32 + n]));
    } else {                       // vw1f
        int f = frag - 112;
        int s = f & 3, jn = f >> 2;
        int n = 8 * jn + g, k0 = 16 * s;
        g_vw1f[f * 32 + lane] = make_uint2(
            pack_half2(vw1[(k0 + 2 * t) * 32 + n],     vw1[(k0 + 2 * t + 1) * 32 + n]),
            pack_half2(vw1[(k0 + 8 + 2 * t) * 32 + n], vw1[(k0 + 9 + 2 * t) * 32 + n]));
    }
}

// ---------------- encoder: h (fragment layout) + p0(fp16) + zero q/cnt ----------------
__global__ __launch_bounds__(256) void encoder_kernel(
    const float* __restrict__ x,  const float* __restrict__ w,
    const float* __restrict__ b,  const float* __restrict__ g,
    const float* __restrict__ beta,
    const float* __restrict__ w1, const float* __restrict__ b1)
{
    __shared__ float hstage[32][68];
    int wl   = threadIdx.x >> 5;
    int lane = threadIdx.x & 31;
    int n0   = blockIdx.x * 32 + wl * 4;
    bool act = (n0 < N_NODES);

    float h0[4], h1[4];
    if (act) {
        float xv[4], a0[4], a1[4];
#pragma unroll
        for (int i = 0; i < 4; i++) {
            xv[i] = (lane < IN_C) ? x[(n0 + i) * IN_C + lane] : 0.0f;
            a0[i] = __ldg(&b[lane]);
            a1[i] = __ldg(&b[lane + 32]);
        }
#pragma unroll
        for (int k = 0; k < IN_C; k++) {
            float w0 = __ldg(&w[k * HDIM + lane]);
            float w1v = __ldg(&w[k * HDIM + 32 + lane]);
#pragma unroll
            for (int i = 0; i < 4; i++) {
                float xk = __shfl_sync(FULL, xv[i], k);
                a0[i] = fmaf(xk, w0, a0[i]);
                a1[i] = fmaf(xk, w1v, a1[i]);
            }
        }
        float gl = __ldg(&g[lane]), gh = __ldg(&g[lane + 32]);
        float bl = __ldg(&beta[lane]), bh = __ldg(&beta[lane + 32]);
#pragma unroll
        for (int i = 0; i < 4; i++) {
            float s1 = a0[i] + a1[i], s2 = a0[i] * a0[i] + a1[i] * a1[i];
#pragma unroll
            for (int o = 16; o; o >>= 1) {
                s1 += __shfl_xor_sync(FULL, s1, o);
                s2 += __shfl_xor_sync(FULL, s2, o);
            }
            float mu  = s1 * (1.0f / 64.0f);
            float var = s2 * (1.0f / 64.0f) - mu * mu;
            float rs  = rsqrtf(var + 1e-5f);
            h0[i] = fmaxf(fmaf((a0[i] - mu) * rs, gl, bl), 0.0f);
            h1[i] = fmaxf(fmaf((a1[i] - mu) * rs, gh, bh), 0.0f);
            hstage[wl * 4 + i][lane]      = h0[i];
            hstage[wl * 4 + i][lane + 32] = h1[i];
        }
        float acc[4];
#pragma unroll
        for (int i = 0; i < 4; i++) acc[i] = __ldg(&b1[lane]);
#pragma unroll
        for (int k = 0; k < 32; k++) {
            float wk = __ldg(&w1[k * HH + lane]);
#pragma unroll
            for (int i = 0; i < 4; i++)
                acc[i] = fmaf(__shfl_sync(FULL, h0[i], k), wk, acc[i]);
        }
#pragma unroll
        for (int k = 0; k < 32; k++) {
            float wk = __ldg(&w1[(32 + k) * HH + lane]);
#pragma unroll
            for (int i = 0; i < 4; i++)
                acc[i] = fmaf(__shfl_sync(FULL, h1[i], k), wk, acc[i]);
        }
        unsigned* ph = (unsigned*)g_ph4;
#pragma unroll
        for (int i = 0; i < 4; i++) {
            float pr = __shfl_xor_sync(FULL, acc[i], 1);
            if ((lane & 1) == 0)
                ph[(size_t)(n0 + i) * 16 + (lane >> 1)] = pack_half2(acc[i], pr);
        }
        if (lane < 16) g_qh4[n0 * 4 + lane] = make_uint4(0, 0, 0, 0);
        if (lane < 4)  g_cnt[n0 + lane] = 0.0f;
    }
    __syncthreads();

    // warps 0,1 write the two 16-node tiles in fragment layout
    if (wl < 2) {
        int tile = blockIdx.x * 2 + wl;
        if (tile < N_TILES) {
            int gq = lane >> 2, tq = lane & 3;
            int r0 = wl * 16 + gq, r1 = r0 + 8;
            float4* hfo = g_hf + (size_t)tile * 256 + lane * 8;
#pragma unroll
            for (int j = 0; j < 8; j++) {
                float2 lo = *(float2*)&hstage[r0][2 * tq + 8 * j];
                float2 hi = *(float2*)&hstage[r1][2 * tq + 8 * j];
                hfo[j] = make_float4(lo.x, lo.y, hi.x, hi.y);
            }
        }
    }
}

// ------- edge kernel: 4-thread group handles 4 edges; W amortized; fp16 RED -------
template<bool COUNT>
__global__ __launch_bounds__(256) void edge_kernel(
    const int* __restrict__ ei, const float* __restrict__ ea,
    const float* __restrict__ w1)
{
    int idx = blockIdx.x * blockDim.x + threadIdx.x;
    int gid = idx >> 2, q0 = idx & 3;
    int e0i = gid * 4;
    if (e0i >= E_EDGES) return;

    // W rows for this thread's two quads, loaded once for 4 edges
    const float4* W = (const float4*)(w1 + 64 * HH);
    float4 wa0 = __ldg(&W[2 * q0]),     wb0 = __ldg(&W[8 + 2 * q0]),     wc0 = __ldg(&W[16 + 2 * q0]);
    float4 wa1 = __ldg(&W[2 * q0 + 1]), wb1 = __ldg(&W[8 + 2 * q0 + 1]), wc1 = __ldg(&W[16 + 2 * q0 + 1]);

    int srcv[4], dstv[4];
    float ev0[4], ev1[4], ev2[4];
#pragma unroll
    for (int j = 0; j < 4; j++) {
        srcv[j] = __ldg(&ei[e0i + j]);
        dstv[j] = __ldg(&ei[E_EDGES + e0i + j]);
        ev0[j]  = __ldg(&ea[(e0i + j) * 3 + 0]);
        ev1[j]  = __ldg(&ea[(e0i + j) * 3 + 1]);
        ev2[j]  = __ldg(&ea[(e0i + j) * 3 + 2]);
    }
    uint4 praw[4];
#pragma unroll
    for (int j = 0; j < 4; j++)
        praw[j] = __ldg(&g_ph4[srcv[j] * 4 + q0]);

#pragma unroll
    for (int j = 0; j < 4; j++) {
        float2 p01 = unpack_half2(praw[j].x);
        float2 p23 = unpack_half2(praw[j].y);
        float2 p45 = unpack_half2(praw[j].z);
        float2 p67 = unpack_half2(praw[j].w);
        float e0 = ev0[j], e1 = ev1[j], e2 = ev2[j];

        float v0 = fmaxf(fmaf(e2, wc0.x, fmaf(e1, wb0.x, fmaf(e0, wa0.x, p01.x))), 0.0f);
        float v1 = fmaxf(fmaf(e2, wc0.y, fmaf(e1, wb0.y, fmaf(e0, wa0.y, p01.y))), 0.0f);
        float v2 = fmaxf(fmaf(e2, wc0.z, fmaf(e1, wb0.z, fmaf(e0, wa0.z, p23.x))), 0.0f);
        float v3 = fmaxf(fmaf(e2, wc0.w, fmaf(e1, wb0.w, fmaf(e0, wa0.w, p23.y))), 0.0f);
        float v4 = fmaxf(fmaf(e2, wc1.x, fmaf(e1, wb1.x, fmaf(e0, wa1.x, p45.x))), 0.0f);
        float v5 = fmaxf(fmaf(e2, wc1.y, fmaf(e1, wb1.y, fmaf(e0, wa1.y, p45.y))), 0.0f);
        float v6 = fmaxf(fmaf(e2, wc1.z, fmaf(e1, wb1.z, fmaf(e0, wa1.z, p67.x))), 0.0f);
        float v7 = fmaxf(fmaf(e2, wc1.w, fmaf(e1, wb1.w, fmaf(e0, wa1.w, p67.y))), 0.0f);

        unsigned u0 = pack_half2(v0, v1);
        unsigned u1 = pack_half2(v2, v3);
        unsigned u2 = pack_half2(v4, v5);
        unsigned u3 = pack_half2(v6, v7);
        __half* qp = (__half*)g_qh4 + (size_t)dstv[j] * 32 + 8 * q0;
        red_add_v4_f16x2(qp, u0, u1, u2, u3);
        if (COUNT && q0 == 0) atomicAdd(&g_cnt[dstv[j]], 1.0f);
    }
}

// ---- node_agg via HMMA (R14 shape): warp = 16-node tile; 8 warps/block ----
template<bool LAST>
__global__ __launch_bounds__(256) void node_agg_kernel(
    int layer,
    const float* __restrict__ b2,  const float* __restrict__ lng,
    const float* __restrict__ lnb, const float* __restrict__ b1n,
    const float* __restrict__ db1, const float* __restrict__ dw2,
    const float* __restrict__ db2, const float* __restrict__ vb1,
    const float* __restrict__ vw2, const float* __restrict__ vb2,
    float* __restrict__ out)
{
    __shared__ __align__(16) char qs[8][1280];
    int tid = threadIdx.x, w = tid >> 5, lane = tid & 31;
    int tile = blockIdx.x * 8 + w;
    if (tile >= N_TILES) return;
    int n0 = tile * 16;
    int g = lane >> 2, tq = lane & 3;

    // stage q fp16 into smem; zero q behind us
    {
        int nl = lane >> 1, half = lane & 1;
        uint4* src = (uint4*)g_qh4 + (size_t)(n0 + nl) * 4 + half * 2;
        uint4 v0 = src[0], v1 = src[1];
        src[0] = make_uint4(0, 0, 0, 0);
        src[1] = make_uint4(0, 0, 0, 0);
        *(uint4*)(qs[w] + nl * 80 + half * 32)      = v0;
        *(uint4*)(qs[w] + nl * 80 + half * 32 + 16) = v1;
    }
    __syncwarp();

    unsigned A0[4], A1[4];
    {
        unsigned base = (unsigned)__cvta_generic_to_shared(qs[w]);
        unsigned addr = base + (lane & 15) * 80 + ((lane >> 4) & 1) * 16;
        ldmx4(A0, addr);
        ldmx4(A1, addr + 32);
    }

    float acc[8][4];
#pragma unroll
    for (int j = 0; j < 8; j++) { acc[j][0] = acc[j][1] = acc[j][2] = acc[j][3] = 0.f; }
    const uint2* w2f = g_w2f + (size_t)layer * 16 * 32;
#pragma unroll
    for (int j = 0; j < 8; j++) {
        uint2 B0 = __ldg(&w2f[(j * 2 + 0) * 32 + lane]);
        uint2 B1 = __ldg(&w2f[(j * 2 + 1) * 32 + lane]);
        hmma(acc[j], A0, B0.x, B0.y);
        hmma(acc[j], A1, B1.x, B1.y);
    }

    float c0 = __ldg(&g_cnt[n0 + g]),     c1 = __ldg(&g_cnt[n0 + 8 + g]);
    float inv0 = (c0 > 0.f) ? (1.f / c0) : 0.f, has0 = (c0 > 0.f) ? 1.f : 0.f;
    float inv1 = (c1 > 0.f) ? (1.f / c1) : 0.f, has1 = (c1 > 0.f) ? 1.f : 0.f;

    const float2* b22 = (const float2*)b2;
    const float4* hf  = g_hf + (size_t)tile * 256 + lane * 8;
    float s10 = 0.f, s20 = 0.f, s11 = 0.f, s21 = 0.f;
#pragma unroll
    for (int j = 0; j < 8; j++) {
        float4 hp = __ldg(&hf[j]);
        float2 bb = __ldg(&b22[tq + 4 * j]);
        acc[j][0] = hp.x + acc[j][0] * inv0 + has0 * bb.x;
        acc[j][1] = hp.y + acc[j][1] * inv0 + has0 * bb.y;
        acc[j][2] = hp.z + acc[j][2] * inv1 + has1 * bb.x;
        acc[j][3] = hp.w + acc[j][3] * inv1 + has1 * bb.y;
        s10 += acc[j][0] + acc[j][1];
        s20 = fmaf(acc[j][0], acc[j][0], fmaf(acc[j][1], acc[j][1], s20));
        s11 += acc[j][2] + acc[j][3];
        s21 = fmaf(acc[j][2], acc[j][2], fmaf(acc[j][3], acc[j][3], s21));
    }
    s10 += __shfl_xor_sync(FULL, s10, 1); s10 += __shfl_xor_sync(FULL, s10, 2);
    s20 += __shfl_xor_sync(FULL, s20, 1); s20 += __shfl_xor_sync(FULL, s20, 2);
    s11 += __shfl_xor_sync(FULL, s11, 1); s11 += __shfl_xor_sync(FULL, s11, 2);
    s21 += __shfl_xor_sync(FULL, s21, 1); s21 += __shfl_xor_sync(FULL, s21, 2);
    float mu0 = s10 * (1.f / 64.f), var0 = s20 * (1.f / 64.f) - mu0 * mu0;
    float mu1 = s11 * (1.f / 64.f), var1 = s21 * (1.f / 64.f) - mu1 * mu1;
    float rs0 = rsqrtf(var0 + 1e-5f), rs1 = rsqrtf(var1 + 1e-5f);

    const float2* lg2 = (const float2*)lng;
    const float2* lb2 = (const float2*)lnb;
    float4* hfo = g_hf + (size_t)tile * 256 + lane * 8;
    unsigned Ah[4][4];
#pragma unroll
    for (int j = 0; j < 8; j++) {
        float2 gg = __ldg(&lg2[tq + 4 * j]);
        float2 bb = __ldg(&lb2[tq + 4 * j]);
        float v0 = fmaf((acc[j][0] - mu0) * rs0, gg.x, bb.x);
        float v1 = fmaf((acc[j][1] - mu0) * rs0, gg.y, bb.y);
        float v2 = fmaf((acc[j][2] - mu1) * rs1, gg.x, bb.x);
        float v3 = fmaf((acc[j][3] - mu1) * rs1, gg.y, bb.y);
        if (!LAST) hfo[j] = make_float4(v0, v1, v2, v3);
        if ((j & 1) == 0) {
            Ah[j >> 1][0] = pack_half2(v0, v1);
            Ah[j >> 1][1] = pack_half2(v2, v3);
        } else {
            Ah[j >> 1][2] = pack_half2(v0, v1);
            Ah[j >> 1][3] = pack_half2(v2, v3);
        }
    }

    if (!LAST) {
        const uint2* w1f = g_w1f + (size_t)(layer + 1) * 16 * 32;
        const float2* b1n2 = (const float2*)b1n;
        unsigned* ph = (unsigned*)g_ph4;
#pragma unroll
        for (int jn = 0; jn < 4; jn++) {
            float p[4] = {0.f, 0.f, 0.f, 0.f};
#pragma unroll
            for (int s = 0; s < 4; s++) {
                uint2 B = __ldg(&w1f[(jn * 4 + s) * 32 + lane]);
                hmma(p, Ah[s], B.x, B.y);
            }
            float2 bb = __ldg(&b1n2[tq + 4 * jn]);
            ph[(size_t)(n0 + g) * 16 + tq + 4 * jn]     = pack_half2(p[0] + bb.x, p[1] + bb.y);
            ph[(size_t)(n0 + 8 + g) * 16 + tq + 4 * jn] = pack_half2(p[2] + bb.x, p[3] + bb.y);
        }
    } else {
        const float2* db12 = (const float2*)db1;
        const float2* vb12 = (const float2*)vb1;
        const float2* dw22 = (const float2*)dw2;
        const float4* vw24 = (const float4*)vw2;
        float ds0 = 0.f, ds1 = 0.f, v00 = 0.f, v01 = 0.f, v10 = 0.f, v11 = 0.f;
#pragma unroll
        for (int jn = 0; jn < 4; jn++) {
            float dh[4] = {0.f, 0.f, 0.f, 0.f}, vh[4] = {0.f, 0.f, 0.f, 0.f};
#pragma unroll
            for (int s = 0; s < 4; s++) {
                uint2 Bd = __ldg(&g_dw1f[(jn * 4 + s) * 32 + lane]);
                uint2 Bv = __ldg(&g_vw1f[(jn * 4 + s) * 32 + lane]);
                hmma(dh, Ah[s], Bd.x, Bd.y);
                hmma(vh, Ah[s], Bv.x, Bv.y);
            }
            float2 dbb = __ldg(&db12[tq + 4 * jn]);
            float2 vbb = __ldg(&vb12[tq + 4 * jn]);
            float r0 = fmaxf(dh[0] + dbb.x, 0.f), r1 = fmaxf(dh[1] + dbb.y, 0.f);
            float r2 = fmaxf(dh[2] + dbb.x, 0.f), r3 = fmaxf(dh[3] + dbb.y, 0.f);
            float2 ww = __ldg(&dw22[tq + 4 * jn]);
            ds0 = fmaf(r0, ww.x, fmaf(r1, ww.y, ds0));
            ds1 = fmaf(r2, ww.x, fmaf(r3, ww.y, ds1));
            float q0v = fmaxf(vh[0] + vbb.x, 0.f), q1v = fmaxf(vh[1] + vbb.y, 0.f);
            float q2v = fmaxf(vh[2] + vbb.x, 0.f), q3v = fmaxf(vh[3] + vbb.y, 0.f);
            float4 vv = __ldg(&vw24[tq + 4 * jn]);
            v00 = fmaf(q0v, vv.x, fmaf(q1v, vv.z, v00));
            v01 = fmaf(q0v, vv.y, fmaf(q1v, vv.w, v01));
            v10 = fmaf(q2v, vv.x, fmaf(q3v, vv.z, v10));
            v11 = fmaf(q2v, vv.y, fmaf(q3v, vv.w, v11));
        }
        ds0 += __shfl_xor_sync(FULL, ds0, 1); ds0 += __shfl_xor_sync(FULL, ds0, 2);
        ds1 += __shfl_xor_sync(FULL, ds1, 1); ds1 += __shfl_xor_sync(FULL, ds1, 2);
        v00 += __shfl_xor_sync(FULL, v00, 1); v00 += __shfl_xor_sync(FULL, v00, 2);
        v01 += __shfl_xor_sync(FULL, v01, 1); v01 += __shfl_xor_sync(FULL, v01, 2);
        v10 += __shfl_xor_sync(FULL, v10, 1); v10 += __shfl_xor_sync(FULL, v10, 2);
        v11 += __shfl_xor_sync(FULL, v11, 1); v11 += __shfl_xor_sync(FULL, v11, 2);
        if (tq == 0) {
            float d2 = __ldg(&db2[0]);
            float vb0 = __ldg(&vb2[0]), vb1v = __ldg(&vb2[1]);
            out[n0 + g]     = ds0 + d2;
            out[n0 + 8 + g] = ds1 + d2;
            float2* vout = (float2*)(out + N_NODES);
            vout[n0 + g]     = make_float2(v00 + vb0, v01 + vb1v);
            vout[n0 + 8 + g] = make_float2(v10 + vb0, v11 + vb1v);
        }
    }
}

// ---------------- launch ----------------
extern "C" void kernel_launch(void* const* d_in, const int* in_sizes, int n_in,
                              void* d_out, int out_size)
{
    const float* x       = (const float*)d_in[0];
    const int*   ei      = (const int*)  d_in[1];
    const float* ea      = (const float*)d_in[2];
    const float* enc_w   = (const float*)d_in[3];
    const float* enc_b   = (const float*)d_in[4];
    const float* enc_g   = (const float*)d_in[5];
    const float* enc_bt  = (const float*)d_in[6];
    const float* mlp_w1  = (const float*)d_in[7];   // [L, 67, 32]
    const float* mlp_b1  = (const float*)d_in[8];   // [L, 32]
    const float* mlp_w2  = (const float*)d_in[9];   // [L, 32, 64]
    const float* mlp_b2  = (const float*)d_in[10];  // [L, 64]
    const float* ln_g    = (const float*)d_in[11];  // [L, 64]
    const float* ln_b    = (const float*)d_in[12];  // [L, 64]
    const float* dw1     = (const float*)d_in[13];
    const float* db1     = (const float*)d_in[14];
    const float* dw2     = (const float*)d_in[15];
    const float* db2     = (const float*)d_in[16];
    const float* vw1     = (const float*)d_in[17];
    const float* vb1     = (const float*)d_in[18];
    const float* vw2     = (const float*)d_in[19];
    const float* vb2     = (const float*)d_in[20];
    float* out = (float*)d_out;

    const int TB = 256;
    const int enc_grid  = (N_NODES + 31) / 32;
    const int node_grid = (N_TILES + 7) / 8;
    const int edge_grid = (E_EDGES + TB - 1) / TB;   // 4-thread group per 4 edges

    pack_kernel<<<16, TB>>>(mlp_w1, mlp_w2, dw1, vw1);
    encoder_kernel<<<enc_grid, TB>>>(x, enc_w, enc_b, enc_g, enc_bt,
                                     mlp_w1, mlp_b1);

    for (int i = 0; i < NLAYERS; i++) {
        const float* w1 = mlp_w1 + (size_t)i * (HDIM + 3) * HH;
        const float* b2 = mlp_b2 + (size_t)i * HDIM;
        const float* lg = ln_g   + (size_t)i * HDIM;
        const float* lb = ln_b   + (size_t)i * HDIM;
        const float* b1n = mlp_b1 + (size_t)(i + 1) * HH;

        if (i == 0) edge_kernel<true ><<<edge_grid, TB>>>(ei, ea, w1);
        else        edge_kernel<false><<<edge_grid, TB>>>(ei, ea, w1);

        if (i + 1 < NLAYERS)
            node_agg_kernel<false><<<node_grid, TB>>>(i, b2, lg, lb, b1n,
                db1, dw2, db2, vb1, vw2, vb2, out);
        else
            node_agg_kernel<true ><<<node_grid, TB>>>(i, b2, lg, lb, nullptr,
                db1, dw2, db2, vb1, vw2, vb2, out);
    }
}